// round 15
// baseline (speedup 1.0000x reference)
#include <cuda_runtime.h>
#include <cuda_fp16.h>
#include <math.h>
#include <stdint.h>

#define B_      16
#define CIN     512
#define COUT    512
#define T_      2048
#define KW      3
#define LIN_SCALE  0.0625f
#define CONV_SCALE 1.4731391274719738e-2f
#define CONV_SCALE2 (1.0f/4608.0f)

#define NCH     16                 // K chunks (512 / 32)
#define ROWB    80                 // padded row stride (conflict-free ldmatrix)
#define A_TILE  (128 * ROWB)       // 10240 B  (128 o rows x 32 i fp16)
#define BP_TILE (64 * ROWB)        // 5120 B   (64 tp rows x 32 i fp16)
#define STAGE   (4 * A_TILE + 4 * BP_TILE)   // 61440 B
#define NSTG    2
#define SMEM_TOTAL (1024 + NSTG * STAGE)     // 123904 B

// ---- device scratch (allocation-free rule) ----
__device__ float g_s[B_ * CIN];
__device__ float g_demod[B_ * COUT];
// Winograd weight images: [(ph*4 + ot)*16 + ch] tiles of 128 x 80B  (~2.6 MB)
__device__ __align__(1024) char g_Wimg[4 * 4 * NCH * A_TILE];
// Winograd data images: [((b*16+tt)*4 + ph)*16 + ch] tiles of 64 x 80B (~84 MB)
__device__ __align__(1024) char g_Ximg[(size_t)B_ * 16 * 4 * NCH * BP_TILE];

// ---------------- PTX helpers (compute_103-safe) ----------------
__device__ __forceinline__ uint32_t smem_u32(const void* p) {
    uint32_t a;
    asm("{ .reg .u64 t; cvta.to.shared.u64 t, %1; cvt.u32.u64 %0, t; }" : "=r"(a) : "l"(p));
    return a;
}
__device__ __forceinline__ uint32_t elect_one() {
    uint32_t p;
    asm volatile("{ .reg .pred p; elect.sync _|p, 0xFFFFFFFF; selp.b32 %0,1,0,p; }" : "=r"(p));
    return p;
}
#define MBAR_INIT(a, n) \
    asm volatile("mbarrier.init.shared.b64 [%0], %1;" :: "r"(a), "r"((uint32_t)(n)) : "memory")
#define MBAR_EXPECT_TX(a, n) \
    asm volatile("mbarrier.arrive.expect_tx.shared.b64 _, [%0], %1;" :: "r"(a), "r"((uint32_t)(n)) : "memory")
#define MBAR_ARRIVE(a) \
    asm volatile("mbarrier.arrive.shared.b64 _, [%0];" :: "r"(a) : "memory")
#define MBAR_WAIT(a, ph) do {                                                  \
    uint32_t _m = (a), _p = (ph), _d;                                          \
    asm volatile("{ .reg .pred p; mbarrier.try_wait.parity.acquire.cta.shared::cta.b64 p, [%1], %2; selp.b32 %0,1,0,p; }" \
                 : "=r"(_d) : "r"(_m), "r"(_p) : "memory");                    \
    if (!_d) {                                                                 \
        asm volatile("{ .reg .pred P1; WL%=: mbarrier.try_wait.parity.acquire.cta.shared::cta.b64 P1, [%0], %1, 0x989680; @P1 bra.uni WD%=; bra.uni WL%=; WD%=: }" \
                     :: "r"(_m), "r"(_p) : "memory");                          \
    } } while (0)
#define BULK_CP(dst, src, nb, mb)                                              \
    asm volatile("cp.async.bulk.shared::cta.global.mbarrier::complete_tx::bytes [%0], [%1], %2, [%3];" \
                 :: "r"((uint32_t)(dst)), "l"(src), "r"((uint32_t)(nb)), "r"((uint32_t)(mb)) : "memory")

#define LDSM_X4(r, addr) \
    asm volatile("ldmatrix.sync.aligned.m8n8.x4.shared.b16 {%0,%1,%2,%3}, [%4];" \
        : "=r"((r)[0]), "=r"((r)[1]), "=r"((r)[2]), "=r"((r)[3]) : "r"(addr))
#define MMA(c, a, b)                                                           \
    asm volatile("mma.sync.aligned.m16n8k16.row.col.f32.f16.f16.f32 "          \
        "{%0,%1,%2,%3}, {%4,%5,%6,%7}, {%8,%9}, {%0,%1,%2,%3};"                \
        : "+f"((c)[0]), "+f"((c)[1]), "+f"((c)[2]), "+f"((c)[3])               \
        : "r"((a)[0]), "r"((a)[1]), "r"((a)[2]), "r"((a)[3]),                  \
          "r"((b)[0]), "r"((b)[1]))

// ---------------- prep kernels ----------------
__global__ void style_kernel(const float* __restrict__ c_src, const float* __restrict__ c_trg,
                             const float* __restrict__ style_w, const float* __restrict__ style_b)
{
    int b = blockIdx.x, i = threadIdx.x;
    __shared__ float c[256];
    if (i < 128)      c[i] = c_src[b * 128 + i];
    else if (i < 256) c[i] = c_trg[b * 128 + (i - 128)];
    __syncthreads();
    const float* row = style_w + (size_t)i * 256;
    float acc = 0.f;
#pragma unroll 8
    for (int j = 0; j < 256; j++) acc += row[j] * c[j];
    g_s[b * CIN + i] = style_b[i] + LIN_SCALE * acc;
}

__global__ void demod_kernel(const float* __restrict__ weight)
{
    int o = blockIdx.x, tid = threadIdx.x;
    float acc[B_];
#pragma unroll
    for (int b = 0; b < B_; b++) acc[b] = 0.f;
    for (int i = tid; i < CIN; i += 256) {
        const float* wp = weight + (size_t)o * (CIN * KW) + i * KW;
        float w0 = wp[0], w1 = wp[1], w2 = wp[2];
        float wsq = w0*w0 + w1*w1 + w2*w2;
#pragma unroll
        for (int b = 0; b < B_; b++) { float sv = g_s[b * CIN + i]; acc[b] += wsq * sv * sv; }
    }
#pragma unroll
    for (int b = 0; b < B_; b++)
#pragma unroll
        for (int off = 16; off; off >>= 1)
            acc[b] += __shfl_down_sync(0xffffffffu, acc[b], off);
    __shared__ float red[8][B_];
    int lane = tid & 31, warp = tid >> 5;
    if (lane == 0)
#pragma unroll
        for (int b = 0; b < B_; b++) red[warp][b] = acc[b];
    __syncthreads();
    if (tid < B_) {
        float t = 0.f;
#pragma unroll
        for (int w = 0; w < 8; w++) t += red[w][tid];
        g_demod[tid * COUT + o] = rsqrtf(CONV_SCALE2 * t + 1e-8f);
    }
}

// weight[o][i][k] -> 4 Winograd phase images Gw_ph[o,i] (fp16)
__global__ void prepw_kernel(const float* __restrict__ weight)
{
    int idx = blockIdx.x * 256 + threadIdx.x;
    if (idx >= COUT * CIN) return;
    int i = idx & (CIN - 1), o = idx >> 9;
    const float* wp = weight + (size_t)idx * KW;
    float w0 = wp[0], w1 = wp[1], w2 = wp[2];
    float gw[4];
    gw[0] = w0;
    gw[1] = 0.5f * (w0 + w1 + w2);
    gw[2] = 0.5f * (w0 - w1 + w2);
    gw[3] = w2;
    int ot = o >> 7, row = o & 127, ch = i >> 5, il = i & 31;
    size_t off = (size_t)row * ROWB + il * 2;
#pragma unroll
    for (int ph = 0; ph < 4; ph++)
        *(__half*)(g_Wimg + (size_t)((ph * 4 + ot) * NCH + ch) * A_TILE + off) =
            __float2half_rn(gw[ph]);
}

// x[b][i][t]*s -> 4 Winograd phase images Bd_ph[i, tp] (fp16), rows=tp
__global__ void prepx_kernel(const float* __restrict__ x)
{
    int ch = blockIdx.x, tt = blockIdx.y, b = blockIdx.z;
    int tid = threadIdx.x, i0 = ch * 32, tbase = tt * 128 - 1;  // u=0 -> t0-1
    __shared__ float tile[32][133];   // 130 used; stride 133 -> conflict-free cols
    for (int idx = tid; idx < 32 * 130; idx += 256) {
        int i = idx / 130, u = idx - i * 130, tg = tbase + u;
        float v = 0.f;
        if (tg >= 0 && tg < T_)
            v = x[((size_t)b * CIN + i0 + i) * T_ + tg] * g_s[b * CIN + i0 + i];
        tile[i][u] = v;
    }
    __syncthreads();
    char* d0 = g_Ximg + (size_t)(((b * 16 + tt) * 4 + 0) * NCH + ch) * BP_TILE;
    for (int idx = tid; idx < 64 * 16; idx += 256) {
        int r = idx >> 4, dp = idx & 15;   // r = local tp, dp = i-pair
        int ia = dp * 2, ib = ia + 1, u = 2 * r;
        float a0 = tile[ia][u], a1 = tile[ia][u+1], a2 = tile[ia][u+2], a3 = tile[ia][u+3];
        float b0 = tile[ib][u], b1 = tile[ib][u+1], b2 = tile[ib][u+2], b3 = tile[ib][u+3];
        __half2 h0 = __floats2half2_rn(a0 - a2, b0 - b2);
        __half2 h1 = __floats2half2_rn(a1 + a2, b1 + b2);
        __half2 h2 = __floats2half2_rn(a2 - a1, b2 - b1);
        __half2 h3 = __floats2half2_rn(a1 - a3, b1 - b3);
        size_t off = (size_t)r * ROWB + dp * 4;
        *(__half2*)(d0 + 0 * (size_t)NCH * BP_TILE + off) = h0;
        *(__half2*)(d0 + 1 * (size_t)NCH * BP_TILE + off) = h1;
        *(__half2*)(d0 + 2 * (size_t)NCH * BP_TILE + off) = h2;
        *(__half2*)(d0 + 3 * (size_t)NCH * BP_TILE + off) = h3;
    }
}

// ---------------- main GEMM kernel ----------------
// 9 warps: 0-7 compute in 4(o) x 2(tp) grid (m32 x n32tp each), 8 = producer.
// 4 Winograd phase GEMMs accumulate into 4 accumulator sets; epilogue combines
// y0 = M0+M1+M2, y1 = M1-M2-M3 and interleaves t = 2*tp, 2*tp+1.
// Pipeline control flow identical to the proven Round-5/9/10/13 kernel.
__global__ void __launch_bounds__(288, 1)
gemm_kernel(float* __restrict__ out)
{
    extern __shared__ __align__(1024) char smem[];
    const uint32_t sb = smem_u32(smem);
    int tid = threadIdx.x, wid = tid >> 5, lane = tid & 31;
    int tt = blockIdx.x, ot = blockIdx.y, b = blockIdx.z;

    if (tid == 0) {
        MBAR_INIT(sb + 0, 1);  MBAR_INIT(sb + 8, 1);
        MBAR_INIT(sb + 16, 8); MBAR_INIT(sb + 24, 8);
    }
    __syncthreads();

    if (wid == 8) {
        if (elect_one()) {
            for (int cc = 0; cc < 8; cc++) {
#pragma unroll
                for (int st = 0; st < 2; st++) {
                    int c = cc * 2 + st;
                    MBAR_WAIT(sb + 16 + st * 8, (cc & 1) ^ 1);
                    MBAR_EXPECT_TX(sb + st * 8, STAGE);
                    uint32_t dbase = sb + 1024 + st * STAGE;
#pragma unroll
                    for (int ph = 0; ph < 4; ph++) {
                        const char* srcA = g_Wimg + (size_t)((ph * 4 + ot) * NCH + c) * A_TILE;
                        BULK_CP(dbase + ph * A_TILE, srcA, A_TILE, sb + st * 8);
                        const char* srcB = g_Ximg + (size_t)(((b * 16 + tt) * 4 + ph) * NCH + c) * BP_TILE;
                        BULK_CP(dbase + 4 * A_TILE + ph * BP_TILE, srcB, BP_TILE, sb + st * 8);
                    }
                }
            }
        }
    } else {
        int wo = wid >> 1;          // 0..3  (o quarter, 32 rows)
        int wt = wid & 1;           // 0..1  (tp half, 32 tp)
        float acc[4][2][4][4];      // [phase][mt][n8 group][4]
#pragma unroll
        for (int ph = 0; ph < 4; ph++)
#pragma unroll
            for (int mt = 0; mt < 2; mt++)
#pragma unroll
                for (int nt = 0; nt < 4; nt++)
#pragma unroll
                    for (int e = 0; e < 4; e++) acc[ph][mt][nt][e] = 0.f;

        const uint32_t aoff = (uint32_t)((wo * 32 + (lane & 15)) * ROWB + (lane >> 4) * 16);
        const uint32_t boff4 = (uint32_t)((wt * 32 + ((lane >> 4) & 1) * 8 + (lane & 7)) * ROWB
                                          + ((lane >> 3) & 1) * 16);

        for (int cc = 0; cc < 8; cc++) {
#pragma unroll
            for (int st = 0; st < 2; st++) {
                MBAR_WAIT(sb + st * 8, cc & 1);
                const uint32_t base = sb + 1024 + st * STAGE;
#pragma unroll
                for (int s = 0; s < 2; s++) {
#pragma unroll
                    for (int ph = 0; ph < 4; ph++) {
                        uint32_t a[2][4];
                        {
                            uint32_t ab = base + ph * A_TILE + aoff + s * 32;
                            LDSM_X4(a[0], ab);
                            LDSM_X4(a[1], ab + 16 * ROWB);
                        }
                        uint32_t bb[2][4];   // [np][n8 pair {k0,k1}]
                        {
                            uint32_t bbs = base + 4 * A_TILE + ph * BP_TILE + boff4 + s * 32;
                            LDSM_X4(bb[0], bbs);
                            LDSM_X4(bb[1], bbs + 16 * ROWB);
                        }
#pragma unroll
                        for (int mt = 0; mt < 2; mt++)
#pragma unroll
                            for (int np = 0; np < 2; np++) {
                                MMA(acc[ph][mt][np * 2 + 0], a[mt], (bb[np] + 0));
                                MMA(acc[ph][mt][np * 2 + 1], a[mt], (bb[np] + 2));
                            }
                    }
                }
                __syncwarp();
                if (lane == 0) MBAR_ARRIVE(sb + 16 + st * 8);
            }
        }

        // ---- epilogue: Winograd output transform + demod scale + store ----
        // lane (g=lane>>2, cg=lane&3): n cols c0 -> tp = nt*8+cg*2, c1 -> +1
        // y(2tp) = M0+M1+M2, y(2tp+1) = M1-M2-M3  -> float4 per (nt, o-row)
        int g = lane >> 2, cg = lane & 3;
        int o_base = ot * 128 + wo * 32;
        int t_base = tt * 128 + wt * 64;
#pragma unroll
        for (int mt = 0; mt < 2; mt++) {
            int o0 = o_base + mt * 16 + g;
            float s0 = CONV_SCALE * g_demod[b * COUT + o0];
            float s1 = CONV_SCALE * g_demod[b * COUT + o0 + 8];
            float* p0 = out + ((size_t)(b * COUT + o0)) * T_ + t_base + 4 * cg;
            float* p1 = p0 + 8 * T_;
#pragma unroll
            for (int nt = 0; nt < 4; nt++) {
                float m0, m1, m2, m3;
                float4 v;
                m0 = acc[0][mt][nt][0]; m1 = acc[1][mt][nt][0];
                m2 = acc[2][mt][nt][0]; m3 = acc[3][mt][nt][0];
                v.x = s0 * (m0 + m1 + m2);  v.y = s0 * (m1 - m2 - m3);
                m0 = acc[0][mt][nt][1]; m1 = acc[1][mt][nt][1];
                m2 = acc[2][mt][nt][1]; m3 = acc[3][mt][nt][1];
                v.z = s0 * (m0 + m1 + m2);  v.w = s0 * (m1 - m2 - m3);
                *(float4*)(p0 + 16 * nt) = v;
                m0 = acc[0][mt][nt][2]; m1 = acc[1][mt][nt][2];
                m2 = acc[2][mt][nt][2]; m3 = acc[3][mt][nt][2];
                v.x = s1 * (m0 + m1 + m2);  v.y = s1 * (m1 - m2 - m3);
                m0 = acc[0][mt][nt][3]; m1 = acc[1][mt][nt][3];
                m2 = acc[2][mt][nt][3]; m3 = acc[3][mt][nt][3];
                v.z = s1 * (m0 + m1 + m2);  v.w = s1 * (m1 - m2 - m3);
                *(float4*)(p1 + 16 * nt) = v;
            }
        }
    }
}

// ---------------- launch ----------------
extern "C" void kernel_launch(void* const* d_in, const int* in_sizes, int n_in,
                              void* d_out, int out_size)
{
    const float* x       = (const float*)d_in[0];
    const float* c_src   = (const float*)d_in[1];
    const float* c_trg   = (const float*)d_in[2];
    const float* style_w = (const float*)d_in[3];
    const float* style_b = (const float*)d_in[4];
    const float* weight  = (const float*)d_in[5];
    float* out = (float*)d_out;

    cudaFuncSetAttribute(gemm_kernel, cudaFuncAttributeMaxDynamicSharedMemorySize, SMEM_TOTAL);

    style_kernel<<<B_, 512>>>(c_src, c_trg, style_w, style_b);
    prepw_kernel<<<(COUT * CIN + 255) / 256, 256>>>(weight);
    demod_kernel<<<COUT, 256>>>(weight);
    prepx_kernel<<<dim3(NCH, 16, B_), 256>>>(x);
    gemm_kernel<<<dim3(16, 4, B_), 288, SMEM_TOTAL>>>(out);
}

// round 17
// speedup vs baseline: 1.0129x; 1.0129x over previous
#include <cuda_runtime.h>
#include <cuda_fp16.h>
#include <math.h>
#include <stdint.h>

#define B_      16
#define CIN     512
#define COUT    512
#define T_      2048
#define KW      3
#define LIN_SCALE  0.0625f
#define CONV_SCALE 1.4731391274719738e-2f
#define CONV_SCALE2 (1.0f/4608.0f)

#define NCH     16                 // K chunks (512 / 32)
#define XROWS   136                // B tile rows: t0-1 .. t0+134
#define ROWB    80                 // padded row stride (conflict-free ldmatrix)
#define A_TILE  (128 * ROWB)       // 10240 B
#define B_TILE  (XROWS * ROWB)     // 10880 B
#define STAGE   (3 * A_TILE + B_TILE)       // 41600 B
#define NSTG    2
#define SMEM_TOTAL (1024 + NSTG * STAGE)    // 84224 B  (2 CTAs/SM fit)

// ---- device scratch (allocation-free rule) ----
__device__ float g_s[B_ * CIN];
__device__ float g_demod[B_ * COUT];
// W images (fp16): [(k*4 + ot)*16 + ch] tiles of 128 x 80B   (~2 MB)
__device__ __align__(1024) char g_Wimg[3 * 4 * NCH * A_TILE];
// X images (fp16): [(b*16+tt)*16 + ch] tiles of 136 x 80B    (~44.6 MB)
__device__ __align__(1024) char g_Ximg[(size_t)B_ * 16 * NCH * B_TILE];

// ---------------- PTX helpers (compute_103-safe) ----------------
__device__ __forceinline__ uint32_t smem_u32(const void* p) {
    uint32_t a;
    asm("{ .reg .u64 t; cvta.to.shared.u64 t, %1; cvt.u32.u64 %0, t; }" : "=r"(a) : "l"(p));
    return a;
}
__device__ __forceinline__ uint32_t elect_one() {
    uint32_t p;
    asm volatile("{ .reg .pred p; elect.sync _|p, 0xFFFFFFFF; selp.b32 %0,1,0,p; }" : "=r"(p));
    return p;
}
#define MBAR_INIT(a, n) \
    asm volatile("mbarrier.init.shared.b64 [%0], %1;" :: "r"(a), "r"((uint32_t)(n)) : "memory")
#define MBAR_EXPECT_TX(a, n) \
    asm volatile("mbarrier.arrive.expect_tx.shared.b64 _, [%0], %1;" :: "r"(a), "r"((uint32_t)(n)) : "memory")
#define MBAR_ARRIVE(a) \
    asm volatile("mbarrier.arrive.shared.b64 _, [%0];" :: "r"(a) : "memory")
#define MBAR_WAIT(a, ph) do {                                                  \
    uint32_t _m = (a), _p = (ph), _d;                                          \
    asm volatile("{ .reg .pred p; mbarrier.try_wait.parity.acquire.cta.shared::cta.b64 p, [%1], %2; selp.b32 %0,1,0,p; }" \
                 : "=r"(_d) : "r"(_m), "r"(_p) : "memory");                    \
    if (!_d) {                                                                 \
        asm volatile("{ .reg .pred P1; WL%=: mbarrier.try_wait.parity.acquire.cta.shared::cta.b64 P1, [%0], %1, 0x989680; @P1 bra.uni WD%=; bra.uni WL%=; WD%=: }" \
                     :: "r"(_m), "r"(_p) : "memory");                          \
    } } while (0)
#define BULK_CP(dst, src, nb, mb)                                              \
    asm volatile("cp.async.bulk.shared::cta.global.mbarrier::complete_tx::bytes [%0], [%1], %2, [%3];" \
                 :: "r"((uint32_t)(dst)), "l"(src), "r"((uint32_t)(nb)), "r"((uint32_t)(mb)) : "memory")

#define LDSM_X4(r, addr) \
    asm volatile("ldmatrix.sync.aligned.m8n8.x4.shared.b16 {%0,%1,%2,%3}, [%4];" \
        : "=r"((r)[0]), "=r"((r)[1]), "=r"((r)[2]), "=r"((r)[3]) : "r"(addr))
#define MMA(c, a, b)                                                           \
    asm volatile("mma.sync.aligned.m16n8k16.row.col.f32.f16.f16.f32 "          \
        "{%0,%1,%2,%3}, {%4,%5,%6,%7}, {%8,%9}, {%0,%1,%2,%3};"                \
        : "+f"((c)[0]), "+f"((c)[1]), "+f"((c)[2]), "+f"((c)[3])               \
        : "r"((a)[0]), "r"((a)[1]), "r"((a)[2]), "r"((a)[3]),                  \
          "r"((b)[0]), "r"((b)[1]))

// ---------------- prep kernels ----------------
__global__ void style_kernel(const float* __restrict__ c_src, const float* __restrict__ c_trg,
                             const float* __restrict__ style_w, const float* __restrict__ style_b)
{
    int b = blockIdx.x, i = threadIdx.x;
    __shared__ float c[256];
    if (i < 128)      c[i] = c_src[b * 128 + i];
    else if (i < 256) c[i] = c_trg[b * 128 + (i - 128)];
    __syncthreads();
    const float* row = style_w + (size_t)i * 256;
    float acc = 0.f;
#pragma unroll 8
    for (int j = 0; j < 256; j++) acc += row[j] * c[j];
    g_s[b * CIN + i] = style_b[i] + LIN_SCALE * acc;
}

__global__ void demod_kernel(const float* __restrict__ weight)
{
    int o = blockIdx.x, tid = threadIdx.x;
    float acc[B_];
#pragma unroll
    for (int b = 0; b < B_; b++) acc[b] = 0.f;
    for (int i = tid; i < CIN; i += 256) {
        const float* wp = weight + (size_t)o * (CIN * KW) + i * KW;
        float w0 = wp[0], w1 = wp[1], w2 = wp[2];
        float wsq = w0*w0 + w1*w1 + w2*w2;
#pragma unroll
        for (int b = 0; b < B_; b++) { float sv = g_s[b * CIN + i]; acc[b] += wsq * sv * sv; }
    }
#pragma unroll
    for (int b = 0; b < B_; b++)
#pragma unroll
        for (int off = 16; off; off >>= 1)
            acc[b] += __shfl_down_sync(0xffffffffu, acc[b], off);
    __shared__ float red[8][B_];
    int lane = tid & 31, warp = tid >> 5;
    if (lane == 0)
#pragma unroll
        for (int b = 0; b < B_; b++) red[warp][b] = acc[b];
    __syncthreads();
    if (tid < B_) {
        float t = 0.f;
#pragma unroll
        for (int w = 0; w < 8; w++) t += red[w][tid];
        g_demod[tid * COUT + o] = rsqrtf(CONV_SCALE2 * t + 1e-8f);
    }
}

// weight[o][i][k] -> A tile images (fp16), rows=o (80B), cols=i
__global__ void prepw_kernel(const float* __restrict__ weight)
{
    int idx = blockIdx.x * 256 + threadIdx.x;
    if (idx >= KW * COUT * CIN) return;
    int i = idx & (CIN - 1);
    int o = (idx >> 9) & (COUT - 1);
    int k = idx >> 18;
    float v = weight[((size_t)o * CIN + i) * KW + k];
    __half hh = __float2half_rn(v);
    int ot = o >> 7, row = o & 127, ch = i >> 5, il = i & 31;
    size_t off = (size_t)row * ROWB + il * 2;
    size_t th = (size_t)((k * 4 + ot) * NCH + ch) * A_TILE;
    *(__half*)(g_Wimg + th + off) = hh;
}

// x[b][i][t]*s -> B tile images (fp16), rows=t (t0-1..t0+134, 80B), cols=i.
// Lean version: fixed (row, col-phase) thread mapping, block-level bounds
// hoist (interior tiles guard-free), g_s hoisted to one load per thread.
__global__ void prepx_kernel(const float* __restrict__ x)
{
    int ch = blockIdx.x, tt = blockIdx.y, b = blockIdx.z;
    int tid = threadIdx.x, i0 = ch * 32, tbase = tt * 128 - 1;
    __shared__ float tile[32][137];   // conflict-free column reads in write phase

    int i = tid >> 3;                 // 0..31 (row)
    int c0 = tid & 7;                 // col phase; cols c0, c0+8, ..., c0+128 (17)
    const float* xr = x + ((size_t)b * CIN + i0 + i) * T_ + tbase;
    float sv = g_s[b * CIN + i0 + i];

    if (tt != 0 && tt != 15) {        // interior: t range fully in-bounds
#pragma unroll
        for (int j = 0; j < 17; j++) {
            int r = c0 + j * 8;
            tile[i][r] = xr[r] * sv;
        }
    } else {
#pragma unroll
        for (int j = 0; j < 17; j++) {
            int r = c0 + j * 8, tg = tbase + r;
            tile[i][r] = (tg >= 0 && tg < T_) ? xr[r] * sv : 0.f;
        }
    }
    __syncthreads();

    char* dst = g_Ximg + (size_t)((b * 16 + tt) * NCH + ch) * B_TILE;
    for (int idx = tid; idx < XROWS * 16; idx += 256) {
        int r = idx >> 4, dp = idx & 15;
        __half2 h = __floats2half2_rn(tile[dp * 2][r], tile[dp * 2 + 1][r]);
        *(__half2*)(dst + r * ROWB + dp * 4) = h;
    }
}

// ---------------- main GEMM kernel (proven Round-13 version) ----------------
// 9 warps: 0-7 compute in a 4(o) x 2(t) grid (m32 x n64 each), 8 = producer.
__global__ void __launch_bounds__(288, 2)
gemm_kernel(float* __restrict__ out)
{
    extern __shared__ __align__(1024) char smem[];
    const uint32_t sb = smem_u32(smem);
    int tid = threadIdx.x, wid = tid >> 5, lane = tid & 31;
    int tt = blockIdx.x, ot = blockIdx.y, b = blockIdx.z;

    if (tid == 0) {
        MBAR_INIT(sb + 0, 1);  MBAR_INIT(sb + 8, 1);
        MBAR_INIT(sb + 16, 8); MBAR_INIT(sb + 24, 8);
    }
    __syncthreads();

    if (wid == 8) {
        if (elect_one()) {
            for (int cc = 0; cc < 8; cc++) {
#pragma unroll
                for (int st = 0; st < 2; st++) {
                    int c = cc * 2 + st;
                    MBAR_WAIT(sb + 16 + st * 8, (cc & 1) ^ 1);
                    MBAR_EXPECT_TX(sb + st * 8, STAGE);
                    uint32_t dbase = sb + 1024 + st * STAGE;
#pragma unroll
                    for (int k = 0; k < 3; k++) {
                        const char* src = g_Wimg + (size_t)((k * 4 + ot) * NCH + c) * A_TILE;
                        BULK_CP(dbase + k * A_TILE, src, A_TILE, sb + st * 8);
                    }
                    {
                        const char* src = g_Ximg + (size_t)((b * 16 + tt) * NCH + c) * B_TILE;
                        BULK_CP(dbase + 3 * A_TILE, src, B_TILE, sb + st * 8);
                    }
                }
            }
        }
    } else {
        int wo = wid >> 1;          // 0..3  (o quarter, 32 rows)
        int wt = wid & 1;           // 0..1  (t half, 64 cols)
        float acc[2][8][4];
#pragma unroll
        for (int mt = 0; mt < 2; mt++)
#pragma unroll
            for (int nt = 0; nt < 8; nt++)
#pragma unroll
                for (int e = 0; e < 4; e++) acc[mt][nt][e] = 0.f;

        const uint32_t aoff = (uint32_t)((wo * 32 + (lane & 15)) * ROWB + (lane >> 4) * 16);
        const uint32_t boff4 = (uint32_t)((wt * 64 + ((lane >> 4) & 1) * 8 + (lane & 7)) * ROWB
                                          + ((lane >> 3) & 1) * 16);

        for (int cc = 0; cc < 8; cc++) {
#pragma unroll
            for (int st = 0; st < 2; st++) {
                MBAR_WAIT(sb + st * 8, cc & 1);
                const uint32_t base = sb + 1024 + st * STAGE;
#pragma unroll
                for (int s = 0; s < 2; s++) {
#pragma unroll
                    for (int k = 0; k < 3; k++) {
                        uint32_t a[2][4];
                        {
                            uint32_t ab = base + k * A_TILE + aoff + s * 32;
                            LDSM_X4(a[0], ab);
                            LDSM_X4(a[1], ab + 16 * ROWB);
                        }
                        uint32_t bb[4][4];   // [nt-pair][nt0{k0,k1}, nt1{k0,k1}]
                        {
                            uint32_t bbs = base + 3 * A_TILE + boff4 + k * ROWB + s * 32;
#pragma unroll
                            for (int np = 0; np < 4; np++)
                                LDSM_X4(bb[np], bbs + np * (16 * ROWB));
                        }
#pragma unroll
                        for (int mt = 0; mt < 2; mt++)
#pragma unroll
                            for (int np = 0; np < 4; np++) {
                                MMA(acc[mt][np * 2 + 0], a[mt], (bb[np] + 0));
                                MMA(acc[mt][np * 2 + 1], a[mt], (bb[np] + 2));
                            }
                    }
                }
                __syncwarp();
                if (lane == 0) MBAR_ARRIVE(sb + 16 + st * 8);
            }
        }

        // ---- epilogue: scale by CONV_SCALE*demod, store ----
        int g = lane >> 2, cg = lane & 3;
        int o_base = ot * 128 + wo * 32;
        int t_base = tt * 128 + wt * 64;
#pragma unroll
        for (int mt = 0; mt < 2; mt++) {
            int o0 = o_base + mt * 16 + g;
            float s0 = CONV_SCALE * g_demod[b * COUT + o0];
            float s1 = CONV_SCALE * g_demod[b * COUT + o0 + 8];
            float* p0 = out + ((size_t)(b * COUT + o0)) * T_ + t_base + cg * 2;
            float* p1 = p0 + 8 * T_;
#pragma unroll
            for (int nt = 0; nt < 8; nt++) {
                float2 v0 = make_float2(acc[mt][nt][0] * s0, acc[mt][nt][1] * s0);
                float2 v1 = make_float2(acc[mt][nt][2] * s1, acc[mt][nt][3] * s1);
                *(float2*)(p0 + nt * 8) = v0;
                *(float2*)(p1 + nt * 8) = v1;
            }
        }
    }
}

// ---------------- launch ----------------
extern "C" void kernel_launch(void* const* d_in, const int* in_sizes, int n_in,
                              void* d_out, int out_size)
{
    const float* x       = (const float*)d_in[0];
    const float* c_src   = (const float*)d_in[1];
    const float* c_trg   = (const float*)d_in[2];
    const float* style_w = (const float*)d_in[3];
    const float* style_b = (const float*)d_in[4];
    const float* weight  = (const float*)d_in[5];
    float* out = (float*)d_out;

    cudaFuncSetAttribute(gemm_kernel, cudaFuncAttributeMaxDynamicSharedMemorySize, SMEM_TOTAL);

    style_kernel<<<B_, 512>>>(c_src, c_trg, style_w, style_b);
    prepx_kernel<<<dim3(NCH, 16, B_), 256>>>(x);
    prepw_kernel<<<(KW * COUT * CIN + 255) / 256, 256>>>(weight);
    demod_kernel<<<COUT, 256>>>(weight);
    gemm_kernel<<<dim3(16, 4, B_), 288, SMEM_TOTAL>>>(out);
}